// round 11
// baseline (speedup 1.0000x reference)
#include <cuda_runtime.h>
#include <cuda_fp16.h>
#include <math.h>
#include <stdint.h>

// Problem constants (fixed shapes per reference)
#define N_D   4096
#define N_M   8192
#define NN    12288          // N_D + N_M
#define EE    196608
#define KHOP  4
#define HIDD  512
#define LDF   2560           // HID*(K+1)

// ---------------- device scratch ------------------------------------------
__device__ int   g_deg[NN];
__device__ float g_norm[NN];
__device__ int   g_offs[NN + 1];
__device__ int   g_cursor[NN];
__device__ int   g_csr_src[EE];
__device__ float g_csr_w[EE];
__device__ float g_h[(size_t)NN * HIDD];                  // [N, 512] fp32
__device__ __half g_Fh[(size_t)NN * LDF];                 // feat, fp16
__device__ __half g_Bt[(size_t)512 * (N_D + N_M + LDF)];  // W^T fp16 (d|m|f)
// fp16 copies of the two similarity matrices: d at 0, m at N_D*N_D
__device__ __half g_Ah[(size_t)N_D * N_D + (size_t)N_M * N_M];

// ---------------- PTX helpers (plain sm_103-safe) ---------------------------
__device__ __forceinline__ uint32_t smem_u32(const void* p) {
    uint32_t a;
    asm("{ .reg .u64 t; cvta.to.shared.u64 t, %1; cvt.u32.u64 %0, t; }"
        : "=r"(a) : "l"(p));
    return a;
}

__device__ __forceinline__ void cpasync16(uint32_t dst, const void* src) {
    asm volatile("cp.async.cg.shared.global [%0], [%1], 16;" :: "r"(dst), "l"(src));
}
__device__ __forceinline__ void cp_commit() {
    asm volatile("cp.async.commit_group;" ::: "memory");
}
template <int N>
__device__ __forceinline__ void cp_wait() {
    asm volatile("cp.async.wait_group %0;" :: "n"(N) : "memory");
}

__device__ __forceinline__ void ldsm_x4(uint32_t addr, uint32_t& r0, uint32_t& r1,
                                        uint32_t& r2, uint32_t& r3) {
    asm volatile("ldmatrix.sync.aligned.m8n8.x4.shared.b16 {%0,%1,%2,%3}, [%4];"
                 : "=r"(r0), "=r"(r1), "=r"(r2), "=r"(r3) : "r"(addr));
}

__device__ __forceinline__ void mma16816(float* c, const uint32_t* a, const uint32_t* b) {
    asm volatile(
        "mma.sync.aligned.m16n8k16.row.col.f32.f16.f16.f32 "
        "{%0,%1,%2,%3}, {%4,%5,%6,%7}, {%8,%9}, {%0,%1,%2,%3};"
        : "+f"(c[0]), "+f"(c[1]), "+f"(c[2]), "+f"(c[3])
        : "r"(a[0]), "r"(a[1]), "r"(a[2]), "r"(a[3]), "r"(b[0]), "r"(b[1]));
}

// ---------------- graph-prep kernels ---------------------------------------
__global__ void zero_kernel() {
    int i = blockIdx.x * blockDim.x + threadIdx.x;
    if (i < NN) { g_deg[i] = 0; g_cursor[i] = 0; }
}

__global__ void deg_kernel(const int* __restrict__ dst, int E) {
    int e = blockIdx.x * blockDim.x + threadIdx.x;
    if (e < E) atomicAdd(&g_deg[dst[e]], 1);
}

// fused norm + exclusive scan (single block, warp-shuffle hierarchy)
__global__ __launch_bounds__(1024) void normscan_kernel() {
    int tid = threadIdx.x;
    int lane = tid & 31, wid = tid >> 5;
    int vals[12];
    int base = tid * 12;
    int s = 0;
    #pragma unroll
    for (int j = 0; j < 12; j++) { vals[j] = g_deg[base + j]; s += vals[j]; }
    int x = s;
    #pragma unroll
    for (int o = 1; o < 32; o <<= 1) {
        int y = __shfl_up_sync(0xffffffffu, x, o);
        if (lane >= o) x += y;
    }
    __shared__ int wsum[32];
    if (lane == 31) wsum[wid] = x;
    __syncthreads();
    if (wid == 0) {
        int w = wsum[lane];
        #pragma unroll
        for (int o = 1; o < 32; o <<= 1) {
            int y = __shfl_up_sync(0xffffffffu, w, o);
            if (lane >= o) w += y;
        }
        wsum[lane] = w;
    }
    __syncthreads();
    int run = x - s + (wid ? wsum[wid - 1] : 0);
    #pragma unroll
    for (int j = 0; j < 12; j++) { g_offs[base + j] = run; run += vals[j]; }
    if (tid == 1023) g_offs[NN] = run;
    for (int i = tid; i < NN; i += 1024) {
        int d = g_deg[i];
        g_norm[i] = rsqrtf((float)(d > 0 ? d : 1));
    }
}

__global__ void fill_kernel(const int* __restrict__ src, const int* __restrict__ dst, int E) {
    int e = blockIdx.x * blockDim.x + threadIdx.x;
    if (e < E) {
        int d = dst[e];
        int s = src[e];
        int p = g_offs[d] + atomicAdd(&g_cursor[d], 1);
        g_csr_src[p] = s;
        g_csr_w[p]   = g_norm[s] * g_norm[d];
    }
}

// ---------------- SpMM hop: fp16 gather over CSR, fp32 accumulate ----------
__global__ void hop_kernel(int col_in, int col_out) {
    int v = blockIdx.x;
    int t = threadIdx.x;
    int s0 = g_offs[v], s1 = g_offs[v + 1];
    __shared__ int   s_src[256];
    __shared__ float s_w[256];
    float a0 = 0.f, a1 = 0.f;
    for (int base = s0; base < s1; base += 256) {
        int n = min(256, s1 - base);
        __syncthreads();
        if (t < n) { s_src[t] = g_csr_src[base + t]; s_w[t] = g_csr_w[base + t]; }
        __syncthreads();
        for (int i = 0; i < n; i++) {
            const __half2* row = reinterpret_cast<const __half2*>(
                g_Fh + (size_t)s_src[i] * LDF + col_in);
            float w = s_w[i];
            float2 p = __half22float2(row[t]);
            a0 += w * p.x;
            a1 += w * p.y;
        }
    }
    *reinterpret_cast<__half2*>(g_Fh + (size_t)v * LDF + col_out + 2 * t) =
        __floats2half2_rn(a0, a1);
}

// ---------------- fp32 -> fp16 convert: d_sim and m_sim in one launch ------
#define ND4 (N_D * N_D / 4)
#define NM4 (N_M * N_M / 4)
__global__ void cvtA_all(const float* __restrict__ Ad, const float* __restrict__ Am,
                         __half* __restrict__ out)
{
    int i = blockIdx.x * blockDim.x + threadIdx.x;
    const float* A; size_t o4;
    if (i < ND4) { A = Ad; o4 = (size_t)i; }
    else if (i < ND4 + NM4) { A = Am - (size_t)ND4 * 0; o4 = (size_t)i; A = Am; o4 = i - ND4; }
    else return;
    float4 v = reinterpret_cast<const float4*>(A)[o4];
    uint2 p;
    __half2* hp = reinterpret_cast<__half2*>(&p);
    hp[0] = __floats2half2_rn(v.x, v.y);
    hp[1] = __floats2half2_rn(v.z, v.w);
    reinterpret_cast<uint2*>(out)[i] = p;
}

// ---------------- fused weight transpose: Wd|Wm|Wf -> [512,K] fp16 ----------
__global__ void cvtBT_all(const float* __restrict__ Wd, const float* __restrict__ Wm,
                          const float* __restrict__ Wf, __half* __restrict__ o)
{
    const float* W; int K; size_t offs;
    int z = blockIdx.z;
    if (z == 0)      { W = Wd; K = N_D; offs = 0; }
    else if (z == 1) { W = Wm; K = N_M; offs = (size_t)512 * N_D; }
    else             { W = Wf; K = LDF; offs = (size_t)512 * (N_D + N_M); }
    int k0 = blockIdx.y * 32;
    if (k0 >= K) return;

    __shared__ float t[32][33];
    int n0 = blockIdx.x * 32;
    int tx = threadIdx.x, ty = threadIdx.y;  // 32 x 8
    #pragma unroll
    for (int r = 0; r < 32; r += 8)
        t[ty + r][tx] = W[(size_t)(k0 + ty + r) * HIDD + n0 + tx];
    __syncthreads();
    #pragma unroll
    for (int r = 0; r < 32; r += 8)
        o[offs + (size_t)(n0 + ty + r) * K + k0 + tx] = __float2half_rn(t[tx][ty + r]);
}

// ---------------- fp16 HMMA GEMM core ---------------------------------------
// 128x128 tile, 256 threads, BK=64 (two 32-k subtiles), 3-stage cp.async,
// __launch_bounds__(256,2) -> 2 CTAs/SM. One barrier per 64 k-steps.
#define GSTG 3
#define TILE32   8192                  // one 128x32 fp16 tile
#define STAGE_B2 (4 * TILE32)          // A(2 subtiles) + B(2 subtiles) = 32 KB
#define GEMM_SMEM (GSTG * STAGE_B2)    // 96 KB

// mode 0: fused d/m (A from g_Ah, by<64 -> m, else d; fp16 out to g_Fh)
// mode 1: f (A, B, K from args; fp32 out to C with bias)
__global__ __launch_bounds__(256, 2) void gemm_core(
    const __half* __restrict__ Aall, const __half* __restrict__ Bt,
    int Kin, float* __restrict__ C, const float* __restrict__ bias, int mode)
{
    extern __shared__ char dynsm[];
    const uint32_t sbase = smem_u32(dynsm);

    const int tid = threadIdx.x;
    const int wid = tid >> 5;
    const int lid = tid & 31;
    const int wm  = wid >> 1;
    const int wn  = wid & 1;
    const int by  = blockIdx.y;
    const int nb0 = blockIdx.x * 128;

    const __half* A; const __half* Bh; int K; int crow;
    if (mode == 0) {
        if (by < 64) {   // m tiles first (longer) for better tail packing
            A = Aall + (size_t)N_D * N_D + (size_t)by * 128 * N_M;
            K = N_M; crow = N_D + by * 128;
            Bh = Bt + (size_t)512 * N_D + (size_t)nb0 * K;
        } else {
            A = Aall + (size_t)(by - 64) * 128 * N_D;
            K = N_D; crow = (by - 64) * 128;
            Bh = Bt + (size_t)nb0 * K;
        }
    } else {
        K = Kin; crow = by * 128;
        A = Aall + (size_t)crow * K;
        Bh = Bt + (size_t)nb0 * K;
    }
    const int chunks = K >> 6;   // 64-k chunks

    // stage layout: [A0 8K][A1 8K][B0 8K][B1 8K]
    auto load_stage = [&](int stage, int c) {
        const uint32_t sb = sbase + stage * STAGE_B2;
        #pragma unroll
        for (int t2 = 0; t2 < 2; t2++) {            // subtile (k half)
            const int k0 = (c << 6) + (t2 << 5);
            #pragma unroll
            for (int i = 0; i < 2; i++) {
                int idx = tid + (i << 8);
                int row = idx >> 2, ch = idx & 3;
                uint32_t sw = (uint32_t)(ch ^ ((row >> 1) & 3));
                uint32_t off = row * 64 + (sw << 4);
                cpasync16(sb + t2 * TILE32 + off,
                          A + (size_t)row * K + k0 + ch * 8);
                cpasync16(sb + 2 * TILE32 + t2 * TILE32 + off,
                          Bh + (size_t)row * K + k0 + ch * 8);
            }
        }
    };

    float acc[2][8][4] = {};

    #pragma unroll
    for (int s = 0; s < GSTG - 1; s++) { load_stage(s, s); cp_commit(); }

    for (int c = 0; c < chunks; c++) {
        cp_wait<GSTG - 2>();
        __syncthreads();
        const int cl = c + GSTG - 1;
        if (cl < chunks) load_stage(cl % GSTG, cl);
        cp_commit();

        const uint32_t sb = sbase + (c % GSTG) * STAGE_B2;
        #pragma unroll
        for (int ks = 0; ks < 4; ks++) {
            const uint32_t sbA = sb + (ks >> 1) * TILE32;
            const uint32_t sbB = sb + 2 * TILE32 + (ks >> 1) * TILE32;
            const int kk = ks & 1;
            uint32_t aF[2][4], bF[8][2];
            #pragma unroll
            for (int mt = 0; mt < 2; mt++) {
                int row = wm * 32 + mt * 16 + (lid & 15);
                int ch  = kk * 2 + (lid >> 4);
                uint32_t off = row * 64 + ((uint32_t)(ch ^ ((row >> 1) & 3)) << 4);
                ldsm_x4(sbA + off, aF[mt][0], aF[mt][1], aF[mt][2], aF[mt][3]);
            }
            #pragma unroll
            for (int nt2 = 0; nt2 < 4; nt2++) {
                int row = wn * 64 + nt2 * 16 + (lid & 7) + ((lid >> 4) << 3);
                int ch  = kk * 2 + ((lid >> 3) & 1);
                uint32_t off = row * 64 + ((uint32_t)(ch ^ ((row >> 1) & 3)) << 4);
                ldsm_x4(sbB + off,
                        bF[2*nt2][0], bF[2*nt2][1], bF[2*nt2+1][0], bF[2*nt2+1][1]);
            }
            #pragma unroll
            for (int mt = 0; mt < 2; mt++)
                #pragma unroll
                for (int nt = 0; nt < 8; nt++)
                    mma16816(acc[mt][nt], aF[mt], bF[nt]);
        }
    }

    // ---- epilogue
    const int gid = lid >> 2, tig = lid & 3;
    if (mode == 0) {
        #pragma unroll
        for (int mt = 0; mt < 2; mt++) {
            #pragma unroll
            for (int nt = 0; nt < 8; nt++) {
                int r0  = crow + wm * 32 + mt * 16 + gid;
                int col = nb0 + wn * 64 + nt * 8 + tig * 2;
                *reinterpret_cast<__half2*>(g_Fh + (size_t)r0 * LDF + col) =
                    __floats2half2_rn(acc[mt][nt][0], acc[mt][nt][1]);
                *reinterpret_cast<__half2*>(g_Fh + (size_t)(r0 + 8) * LDF + col) =
                    __floats2half2_rn(acc[mt][nt][2], acc[mt][nt][3]);
            }
        }
    } else {
        #pragma unroll
        for (int mt = 0; mt < 2; mt++) {
            #pragma unroll
            for (int nt = 0; nt < 8; nt++) {
                int r0  = crow + wm * 32 + mt * 16 + gid;
                int col = nb0 + wn * 64 + nt * 8 + tig * 2;
                float2 bb = *reinterpret_cast<const float2*>(bias + col);
                float2 v0 = make_float2(acc[mt][nt][0] + bb.x, acc[mt][nt][1] + bb.y);
                float2 v1 = make_float2(acc[mt][nt][2] + bb.x, acc[mt][nt][3] + bb.y);
                *reinterpret_cast<float2*>(C + (size_t)r0 * HIDD + col)       = v0;
                *reinterpret_cast<float2*>(C + (size_t)(r0 + 8) * HIDD + col) = v1;
            }
        }
    }
}

// ---------------- pair scoring: warp per pair -------------------------------
__global__ void pair_kernel(const int* __restrict__ dis, const int* __restrict__ mir,
                            const float* __restrict__ Wp, const float* __restrict__ bp,
                            float* __restrict__ out, int P)
{
    int warp = (blockIdx.x * blockDim.x + threadIdx.x) >> 5;
    int lane = threadIdx.x & 31;
    if (warp >= P) return;
    int di = dis[warp];
    int mi = mir[warp];
    const float* hd = g_h + (size_t)di * HIDD;
    const float* hm = g_h + (size_t)mi * HIDD;
    float s = 0.f;
    #pragma unroll 4
    for (int c = lane; c < HIDD; c += 32) {
        float a = hd[c], b = hm[c];
        s += a * Wp[c] + b * Wp[HIDD + c] + (a * b) * Wp[2 * HIDD + c];
    }
    #pragma unroll
    for (int o = 16; o; o >>= 1) s += __shfl_xor_sync(0xffffffffu, s, o);
    if (lane == 0) out[warp] = 1.f / (1.f + expf(-(s + bp[0])));
}

// ---------------- launch ----------------------------------------------------
extern "C" void kernel_launch(void* const* d_in, const int* in_sizes, int n_in,
                              void* d_out, int out_size)
{
    const float* d_sim    = (const float*)d_in[0];
    const float* m_sim    = (const float*)d_in[1];
    const int*   src      = (const int*)  d_in[2];
    const int*   dst      = (const int*)  d_in[3];
    const int*   diseases = (const int*)  d_in[4];
    const int*   mirnas   = (const int*)  d_in[5];
    const float* Wd       = (const float*)d_in[6];
    const float* Wm       = (const float*)d_in[7];
    const float* Wf       = (const float*)d_in[8];
    const float* bf       = (const float*)d_in[9];
    const float* Wp       = (const float*)d_in[10];
    const float* bp       = (const float*)d_in[11];
    float*       out      = (float*)d_out;

    const int E = in_sizes[2];
    const int P = in_sizes[4];

    float* hbuf = nullptr;
    __half *Bt = nullptr, *Fh = nullptr, *Ah = nullptr;
    cudaGetSymbolAddress((void**)&hbuf, g_h);
    cudaGetSymbolAddress((void**)&Bt, g_Bt);
    cudaGetSymbolAddress((void**)&Fh, g_Fh);
    cudaGetSymbolAddress((void**)&Ah, g_Ah);

    cudaFuncSetAttribute(gemm_core, cudaFuncAttributeMaxDynamicSharedMemorySize, GEMM_SMEM);

    // launches ordered so gemm_core(dm) is #4 (the one ncu profiles)
    cvtA_all<<<(ND4 + NM4 + 255) / 256, 256>>>(d_sim, m_sim, Ah);               // 1
    cvtBT_all<<<dim3(HIDD / 32, N_M / 32, 3), dim3(32, 8)>>>(Wd, Wm, Wf, Bt);   // 2
    zero_kernel<<<(NN + 255) / 256, 256>>>();                                   // 3
    gemm_core<<<dim3(4, 96), 256, GEMM_SMEM>>>(
        Ah, Bt, 0, nullptr, nullptr, 0);                                        // 4 <- profiled
    deg_kernel<<<(E + 255) / 256, 256>>>(dst, E);                               // 5
    normscan_kernel<<<1, 1024>>>();                                             // 6
    fill_kernel<<<(E + 255) / 256, 256>>>(src, dst, E);                         // 7

    // ---- K hops of normalized gather-sum (fp16 feat, fp32 accumulate)
    for (int hop = 0; hop < KHOP; hop++)
        hop_kernel<<<NN, 256>>>(hop * HIDD, (hop + 1) * HIDD);

    // ---- h = feat @ Wf + bf
    gemm_core<<<dim3(4, 96), 256, GEMM_SMEM>>>(
        Fh, Bt + (size_t)512 * (N_D + N_M), LDF, hbuf, bf, 1);

    // ---- pair prediction with sigmoid
    pair_kernel<<<(P * 32 + 255) / 256, 256>>>(diseases, mirnas, Wp, bp, out, P);
    (void)n_in; (void)out_size;
}

// round 12
// speedup vs baseline: 1.0258x; 1.0258x over previous
#include <cuda_runtime.h>
#include <cuda_fp16.h>
#include <math.h>
#include <stdint.h>

// Problem constants (fixed shapes per reference)
#define N_D   4096
#define N_M   8192
#define NN    12288          // N_D + N_M
#define EE    196608
#define KHOP  4
#define HIDD  512
#define LDF   2560           // HID*(K+1)

// ---------------- device scratch ------------------------------------------
__device__ int   g_deg[NN];
__device__ float g_norm[NN];
__device__ int   g_offs[NN + 1];
__device__ int   g_cursor[NN];
__device__ int   g_csr_src[EE];
__device__ float g_csr_w[EE];
__device__ __half g_hh[(size_t)NN * HIDD];                // [N, 512] fp16 h
__device__ __half g_Fh[(size_t)NN * LDF];                 // feat, fp16
__device__ __half g_Bt[(size_t)512 * (N_D + N_M + LDF)];  // W^T fp16 (d|m|f)
// fp16 copies of the two similarity matrices: d at 0, m at N_D*N_D
__device__ __half g_Ah[(size_t)N_D * N_D + (size_t)N_M * N_M];

// ---------------- PTX helpers (plain sm_103-safe) ---------------------------
__device__ __forceinline__ uint32_t smem_u32(const void* p) {
    uint32_t a;
    asm("{ .reg .u64 t; cvta.to.shared.u64 t, %1; cvt.u32.u64 %0, t; }"
        : "=r"(a) : "l"(p));
    return a;
}

__device__ __forceinline__ void cpasync16(uint32_t dst, const void* src) {
    asm volatile("cp.async.cg.shared.global [%0], [%1], 16;" :: "r"(dst), "l"(src));
}
__device__ __forceinline__ void cp_commit() {
    asm volatile("cp.async.commit_group;" ::: "memory");
}
template <int N>
__device__ __forceinline__ void cp_wait() {
    asm volatile("cp.async.wait_group %0;" :: "n"(N) : "memory");
}

__device__ __forceinline__ void ldsm_x4(uint32_t addr, uint32_t& r0, uint32_t& r1,
                                        uint32_t& r2, uint32_t& r3) {
    asm volatile("ldmatrix.sync.aligned.m8n8.x4.shared.b16 {%0,%1,%2,%3}, [%4];"
                 : "=r"(r0), "=r"(r1), "=r"(r2), "=r"(r3) : "r"(addr));
}

__device__ __forceinline__ void mma16816(float* c, const uint32_t* a, const uint32_t* b) {
    asm volatile(
        "mma.sync.aligned.m16n8k16.row.col.f32.f16.f16.f32 "
        "{%0,%1,%2,%3}, {%4,%5,%6,%7}, {%8,%9}, {%0,%1,%2,%3};"
        : "+f"(c[0]), "+f"(c[1]), "+f"(c[2]), "+f"(c[3])
        : "r"(a[0]), "r"(a[1]), "r"(a[2]), "r"(a[3]), "r"(b[0]), "r"(b[1]));
}

// ---------------- graph-prep kernels ---------------------------------------
__global__ void zero_kernel() {
    int i = blockIdx.x * blockDim.x + threadIdx.x;
    if (i < NN) { g_deg[i] = 0; g_cursor[i] = 0; }
}

__global__ void deg_kernel(const int* __restrict__ dst, int E) {
    int e = blockIdx.x * blockDim.x + threadIdx.x;
    if (e < E) atomicAdd(&g_deg[dst[e]], 1);
}

// fused norm + exclusive scan (single block, warp-shuffle hierarchy)
__global__ __launch_bounds__(1024) void normscan_kernel() {
    int tid = threadIdx.x;
    int lane = tid & 31, wid = tid >> 5;
    int vals[12];
    int base = tid * 12;
    int s = 0;
    #pragma unroll
    for (int j = 0; j < 12; j++) { vals[j] = g_deg[base + j]; s += vals[j]; }
    int x = s;
    #pragma unroll
    for (int o = 1; o < 32; o <<= 1) {
        int y = __shfl_up_sync(0xffffffffu, x, o);
        if (lane >= o) x += y;
    }
    __shared__ int wsum[32];
    if (lane == 31) wsum[wid] = x;
    __syncthreads();
    if (wid == 0) {
        int w = wsum[lane];
        #pragma unroll
        for (int o = 1; o < 32; o <<= 1) {
            int y = __shfl_up_sync(0xffffffffu, w, o);
            if (lane >= o) w += y;
        }
        wsum[lane] = w;
    }
    __syncthreads();
    int run = x - s + (wid ? wsum[wid - 1] : 0);
    #pragma unroll
    for (int j = 0; j < 12; j++) { g_offs[base + j] = run; run += vals[j]; }
    if (tid == 1023) g_offs[NN] = run;
    for (int i = tid; i < NN; i += 1024) {
        int d = g_deg[i];
        g_norm[i] = rsqrtf((float)(d > 0 ? d : 1));
    }
}

__global__ void fill_kernel(const int* __restrict__ src, const int* __restrict__ dst, int E) {
    int e = blockIdx.x * blockDim.x + threadIdx.x;
    if (e < E) {
        int d = dst[e];
        int s = src[e];
        int p = g_offs[d] + atomicAdd(&g_cursor[d], 1);
        g_csr_src[p] = s;
        g_csr_w[p]   = g_norm[s] * g_norm[d];
    }
}

// ---------------- SpMM hop: fp16 gather over CSR, fp32 accumulate ----------
__global__ void hop_kernel(int col_in, int col_out) {
    int v = blockIdx.x;
    int t = threadIdx.x;
    int s0 = g_offs[v], s1 = g_offs[v + 1];
    __shared__ int   s_src[256];
    __shared__ float s_w[256];
    float a0 = 0.f, a1 = 0.f;
    for (int base = s0; base < s1; base += 256) {
        int n = min(256, s1 - base);
        __syncthreads();
        if (t < n) { s_src[t] = g_csr_src[base + t]; s_w[t] = g_csr_w[base + t]; }
        __syncthreads();
        for (int i = 0; i < n; i++) {
            const __half2* row = reinterpret_cast<const __half2*>(
                g_Fh + (size_t)s_src[i] * LDF + col_in);
            float w = s_w[i];
            float2 p = __half22float2(row[t]);
            a0 += w * p.x;
            a1 += w * p.y;
        }
    }
    *reinterpret_cast<__half2*>(g_Fh + (size_t)v * LDF + col_out + 2 * t) =
        __floats2half2_rn(a0, a1);
}

// ---------------- fp32 -> fp16 convert: d_sim and m_sim in one launch ------
#define ND4 (N_D * N_D / 4)
#define NM4 (N_M * N_M / 4)
__global__ void cvtA_all(const float* __restrict__ Ad, const float* __restrict__ Am,
                         __half* __restrict__ out)
{
    int i = blockIdx.x * blockDim.x + threadIdx.x;
    const float* A; size_t o4;
    if (i < ND4) { A = Ad; o4 = (size_t)i; }
    else if (i < ND4 + NM4) { A = Am; o4 = i - ND4; }
    else return;
    float4 v = reinterpret_cast<const float4*>(A)[o4];
    uint2 p;
    __half2* hp = reinterpret_cast<__half2*>(&p);
    hp[0] = __floats2half2_rn(v.x, v.y);
    hp[1] = __floats2half2_rn(v.z, v.w);
    reinterpret_cast<uint2*>(out)[i] = p;
}

// ---------------- fused weight transpose: Wd|Wm|Wf -> [512,K] fp16 ----------
__global__ void cvtBT_all(const float* __restrict__ Wd, const float* __restrict__ Wm,
                          const float* __restrict__ Wf, __half* __restrict__ o)
{
    const float* W; int K; size_t offs;
    int z = blockIdx.z;
    if (z == 0)      { W = Wd; K = N_D; offs = 0; }
    else if (z == 1) { W = Wm; K = N_M; offs = (size_t)512 * N_D; }
    else             { W = Wf; K = LDF; offs = (size_t)512 * (N_D + N_M); }
    int k0 = blockIdx.y * 32;
    if (k0 >= K) return;

    __shared__ float t[32][33];
    int n0 = blockIdx.x * 32;
    int tx = threadIdx.x, ty = threadIdx.y;  // 32 x 8
    #pragma unroll
    for (int r = 0; r < 32; r += 8)
        t[ty + r][tx] = W[(size_t)(k0 + ty + r) * HIDD + n0 + tx];
    __syncthreads();
    #pragma unroll
    for (int r = 0; r < 32; r += 8)
        o[offs + (size_t)(n0 + ty + r) * K + k0 + tx] = __float2half_rn(t[tx][ty + r]);
}

// ---------------- fp16 HMMA GEMM core ---------------------------------------
// 128x128 tile, 256 threads, BK=32, 5-stage cp.async,
// __launch_bounds__(256,2) -> 2 CTAs/SM (16 warps).
#define GSTG 5
#define TILE_B   8192                  // one 128x32 fp16 tile
#define STAGE_B2 (2 * TILE_B)          // A + B per stage = 16 KB
#define GEMM_SMEM (GSTG * STAGE_B2)    // 80 KB

// mode 0: fused d/m (A from g_Ah, by<64 -> m, else d; fp16 out to g_Fh)
// mode 1: f (A, B, K from args; fp16 out to g_hh with bias)
__global__ __launch_bounds__(256, 2) void gemm_core(
    const __half* __restrict__ Aall, const __half* __restrict__ Bt,
    int Kin, const float* __restrict__ bias, int mode)
{
    extern __shared__ char dynsm[];
    const uint32_t sbase = smem_u32(dynsm);

    const int tid = threadIdx.x;
    const int wid = tid >> 5;
    const int lid = tid & 31;
    const int wm  = wid >> 1;
    const int wn  = wid & 1;
    const int by  = blockIdx.y;
    const int nb0 = blockIdx.x * 128;

    const __half* A; const __half* Bh; int K; int crow;
    if (mode == 0) {
        if (by < 64) {   // m tiles first (longer) for better tail packing
            A = Aall + (size_t)N_D * N_D + (size_t)by * 128 * N_M;
            K = N_M; crow = N_D + by * 128;
            Bh = Bt + (size_t)512 * N_D + (size_t)nb0 * K;
        } else {
            A = Aall + (size_t)(by - 64) * 128 * N_D;
            K = N_D; crow = (by - 64) * 128;
            Bh = Bt + (size_t)nb0 * K;
        }
    } else {
        K = Kin; crow = by * 128;
        A = Aall + (size_t)crow * K;
        Bh = Bt + (size_t)nb0 * K;
    }
    const int chunks = K >> 5;

    auto load_stage = [&](int stage, int c) {
        const int k0 = c << 5;
        const uint32_t sb = sbase + stage * STAGE_B2;
        #pragma unroll
        for (int i = 0; i < 2; i++) {
            int idx = tid + (i << 8);
            int row = idx >> 2, ch = idx & 3;
            uint32_t sw = (uint32_t)(ch ^ ((row >> 1) & 3));
            uint32_t off = row * 64 + (sw << 4);
            cpasync16(sb + off,          A  + (size_t)row * K + k0 + ch * 8);
            cpasync16(sb + TILE_B + off, Bh + (size_t)row * K + k0 + ch * 8);
        }
    };
    auto ldfrags = [&](uint32_t sb, int ks, uint32_t (*aF)[4], uint32_t (*bF)[2]) {
        #pragma unroll
        for (int mt = 0; mt < 2; mt++) {
            int row = wm * 32 + mt * 16 + (lid & 15);
            int ch  = ks * 2 + (lid >> 4);
            uint32_t off = row * 64 + ((uint32_t)(ch ^ ((row >> 1) & 3)) << 4);
            ldsm_x4(sb + off, aF[mt][0], aF[mt][1], aF[mt][2], aF[mt][3]);
        }
        #pragma unroll
        for (int nt2 = 0; nt2 < 4; nt2++) {
            int row = wn * 64 + nt2 * 16 + (lid & 7) + ((lid >> 4) << 3);
            int ch  = ks * 2 + ((lid >> 3) & 1);
            uint32_t off = row * 64 + ((uint32_t)(ch ^ ((row >> 1) & 3)) << 4);
            ldsm_x4(sb + TILE_B + off,
                    bF[2*nt2][0], bF[2*nt2][1], bF[2*nt2+1][0], bF[2*nt2+1][1]);
        }
    };

    float acc[2][8][4] = {};

    #pragma unroll
    for (int s = 0; s < GSTG - 1; s++) { load_stage(s, s); cp_commit(); }

    for (int c = 0; c < chunks; c++) {
        cp_wait<GSTG - 2>();
        __syncthreads();
        const int cl = c + GSTG - 1;
        if (cl < chunks) load_stage(cl % GSTG, cl);
        cp_commit();

        const uint32_t sb = sbase + (c % GSTG) * STAGE_B2;
        #pragma unroll
        for (int ks = 0; ks < 2; ks++) {
            uint32_t aF[2][4], bF[8][2];
            ldfrags(sb, ks, aF, bF);
            #pragma unroll
            for (int mt = 0; mt < 2; mt++)
                #pragma unroll
                for (int nt = 0; nt < 8; nt++)
                    mma16816(acc[mt][nt], aF[mt], bF[nt]);
        }
    }

    // ---- epilogue (both modes emit fp16)
    const int gid = lid >> 2, tig = lid & 3;
    if (mode == 0) {
        #pragma unroll
        for (int mt = 0; mt < 2; mt++) {
            #pragma unroll
            for (int nt = 0; nt < 8; nt++) {
                int r0  = crow + wm * 32 + mt * 16 + gid;
                int col = nb0 + wn * 64 + nt * 8 + tig * 2;
                *reinterpret_cast<__half2*>(g_Fh + (size_t)r0 * LDF + col) =
                    __floats2half2_rn(acc[mt][nt][0], acc[mt][nt][1]);
                *reinterpret_cast<__half2*>(g_Fh + (size_t)(r0 + 8) * LDF + col) =
                    __floats2half2_rn(acc[mt][nt][2], acc[mt][nt][3]);
            }
        }
    } else {
        #pragma unroll
        for (int mt = 0; mt < 2; mt++) {
            #pragma unroll
            for (int nt = 0; nt < 8; nt++) {
                int r0  = crow + wm * 32 + mt * 16 + gid;
                int col = nb0 + wn * 64 + nt * 8 + tig * 2;
                float2 bb = *reinterpret_cast<const float2*>(bias + col);
                *reinterpret_cast<__half2*>(g_hh + (size_t)r0 * HIDD + col) =
                    __floats2half2_rn(acc[mt][nt][0] + bb.x, acc[mt][nt][1] + bb.y);
                *reinterpret_cast<__half2*>(g_hh + (size_t)(r0 + 8) * HIDD + col) =
                    __floats2half2_rn(acc[mt][nt][2] + bb.x, acc[mt][nt][3] + bb.y);
            }
        }
    }
}

// ---------------- pair scoring: warp per pair, fp16 h -----------------------
__global__ void pair_kernel(const int* __restrict__ dis, const int* __restrict__ mir,
                            const float* __restrict__ Wp, const float* __restrict__ bp,
                            float* __restrict__ out, int P)
{
    int warp = (blockIdx.x * blockDim.x + threadIdx.x) >> 5;
    int lane = threadIdx.x & 31;
    if (warp >= P) return;
    int di = dis[warp];
    int mi = mir[warp];
    const __half2* hd = reinterpret_cast<const __half2*>(g_hh + (size_t)di * HIDD);
    const __half2* hm = reinterpret_cast<const __half2*>(g_hh + (size_t)mi * HIDD);
    float s = 0.f;
    #pragma unroll 4
    for (int c2 = lane; c2 < HIDD / 2; c2 += 32) {
        float2 a = __half22float2(hd[c2]);
        float2 b = __half22float2(hm[c2]);
        int c = 2 * c2;
        s += a.x * Wp[c]     + b.x * Wp[HIDD + c]     + (a.x * b.x) * Wp[2 * HIDD + c];
        s += a.y * Wp[c + 1] + b.y * Wp[HIDD + c + 1] + (a.y * b.y) * Wp[2 * HIDD + c + 1];
    }
    #pragma unroll
    for (int o = 16; o; o >>= 1) s += __shfl_xor_sync(0xffffffffu, s, o);
    if (lane == 0) out[warp] = 1.f / (1.f + expf(-(s + bp[0])));
}

// ---------------- launch ----------------------------------------------------
extern "C" void kernel_launch(void* const* d_in, const int* in_sizes, int n_in,
                              void* d_out, int out_size)
{
    const float* d_sim    = (const float*)d_in[0];
    const float* m_sim    = (const float*)d_in[1];
    const int*   src      = (const int*)  d_in[2];
    const int*   dst      = (const int*)  d_in[3];
    const int*   diseases = (const int*)  d_in[4];
    const int*   mirnas   = (const int*)  d_in[5];
    const float* Wd       = (const float*)d_in[6];
    const float* Wm       = (const float*)d_in[7];
    const float* Wf       = (const float*)d_in[8];
    const float* bf       = (const float*)d_in[9];
    const float* Wp       = (const float*)d_in[10];
    const float* bp       = (const float*)d_in[11];
    float*       out      = (float*)d_out;

    const int E = in_sizes[2];
    const int P = in_sizes[4];

    __half *Bt = nullptr, *Fh = nullptr, *Ah = nullptr;
    cudaGetSymbolAddress((void**)&Bt, g_Bt);
    cudaGetSymbolAddress((void**)&Fh, g_Fh);
    cudaGetSymbolAddress((void**)&Ah, g_Ah);

    cudaFuncSetAttribute(gemm_core, cudaFuncAttributeMaxDynamicSharedMemorySize, GEMM_SMEM);

    // launches ordered so gemm_core(dm) is #4 (the one ncu profiles)
    cvtA_all<<<(ND4 + NM4 + 255) / 256, 256>>>(d_sim, m_sim, Ah);               // 1
    cvtBT_all<<<dim3(HIDD / 32, N_M / 32, 3), dim3(32, 8)>>>(Wd, Wm, Wf, Bt);   // 2
    zero_kernel<<<(NN + 255) / 256, 256>>>();                                   // 3
    gemm_core<<<dim3(4, 96), 256, GEMM_SMEM>>>(Ah, Bt, 0, nullptr, 0);          // 4 <- profiled
    deg_kernel<<<(E + 255) / 256, 256>>>(dst, E);                               // 5
    normscan_kernel<<<1, 1024>>>();                                             // 6
    fill_kernel<<<(E + 255) / 256, 256>>>(src, dst, E);                         // 7

    // ---- K hops of normalized gather-sum (fp16 feat, fp32 accumulate)
    for (int hop = 0; hop < KHOP; hop++)
        hop_kernel<<<NN, 256>>>(hop * HIDD, (hop + 1) * HIDD);

    // ---- h = feat @ Wf + bf  (fp16 out)
    gemm_core<<<dim3(4, 96), 256, GEMM_SMEM>>>(
        Fh, Bt + (size_t)512 * (N_D + N_M), LDF, bf, 1);

    // ---- pair prediction with sigmoid
    pair_kernel<<<(P * 32 + 255) / 256, 256>>>(diseases, mirnas, Wp, bp, out, P);
    (void)n_in; (void)out_size;
}